// round 1
// baseline (speedup 1.0000x reference)
#include <cuda_runtime.h>
#include <math.h>

#define NB    16
#define NP    32768
#define NC    81
#define CM1   80
#define NBINS 8192
#define CAP   8192
#define NCAND 400
#define NOUT  100

// ---------------- scratch (static device globals; no allocation) ----------------
__device__ float              g_m[NB * NP];
__device__ float              g_logs[NB * NP];
__device__ unsigned int       g_hist[NB * NBINS];
__device__ int                g_bt[NB];
__device__ int                g_cnt[NB];
__device__ unsigned long long g_cand[NB * CAP];

__device__ __forceinline__ int binf(float s) {
    int b = (int)floorf((s + 30.0f) * (8192.0f / 40.0f));
    b = b < 0 ? 0 : b;
    b = b > (NBINS - 1) ? (NBINS - 1) : b;
    return b;
}

__device__ __forceinline__ unsigned int okey(float s) {
    unsigned int u = __float_as_uint(s);
    return (u & 0x80000000u) ? ~u : (u | 0x80000000u);
}

// ---------------- K0: zero hist + counters ----------------
__global__ void k_zero() {
    int i = blockIdx.x * blockDim.x + threadIdx.x;
    if (i < NB * NBINS) g_hist[i] = 0u;
    if (i < NB) g_cnt[i] = 0;
}

// ---------------- K1: fused logsumexp + score histogram ----------------
// warp per row of 81 logits; lane loads c, c+32, c+64
__global__ void k_lse_hist(const float* __restrict__ logits) {
    __shared__ unsigned int sh[NBINS];
    const int img = blockIdx.y;
    for (int i = threadIdx.x; i < NBINS; i += blockDim.x) sh[i] = 0u;
    __syncthreads();

    const int lane = threadIdx.x & 31;
    const int gw = (blockIdx.x * blockDim.x + threadIdx.x) >> 5;
    const int nw = (gridDim.x * blockDim.x) >> 5;

    for (int p = gw; p < NP; p += nw) {
        const float* row = logits + ((size_t)img * NP + p) * NC;
        float a = row[lane];
        float b = row[lane + 32];
        float c = (lane < 17) ? row[lane + 64] : -INFINITY;
        float m = fmaxf(fmaxf(a, b), c);
#pragma unroll
        for (int o = 16; o; o >>= 1) m = fmaxf(m, __shfl_down_sync(0xffffffffu, m, o));
        m = __shfl_sync(0xffffffffu, m, 0);
        float s = expf(a - m) + expf(b - m);
        if (lane < 17) s += expf(c - m);
#pragma unroll
        for (int o = 16; o; o >>= 1) s += __shfl_down_sync(0xffffffffu, s, o);
        s = __shfl_sync(0xffffffffu, s, 0);
        float logs = logf(s);
        if (lane == 0) { g_m[img * NP + p] = m; g_logs[img * NP + p] = logs; }
        // foreground classes only (c >= 1)
        if (lane >= 1) atomicAdd(&sh[binf((a - m) - logs)], 1u);
        atomicAdd(&sh[binf((b - m) - logs)], 1u);
        if (lane < 17) atomicAdd(&sh[binf((c - m) - logs)], 1u);
    }
    __syncthreads();
    for (int i = threadIdx.x; i < NBINS; i += blockDim.x) {
        unsigned int v = sh[i];
        if (v) atomicAdd(&g_hist[img * NBINS + i], v);
    }
}

// ---------------- K2: find threshold bin (cum from top >= 400) ----------------
__global__ void k_thresh() {
    int img = blockIdx.x;
    if (threadIdx.x == 0) {
        unsigned int cum = 0;
        int b = NBINS - 1;
        for (; b > 0; b--) {
            cum += g_hist[img * NBINS + b];
            if (cum >= NCAND) break;
        }
        g_bt[img] = b;
    }
}

// ---------------- K3: compact candidates (skip rows whose max < threshold) ----
__global__ void k_compact(const float* __restrict__ logits) {
    const int img = blockIdx.y;
    const int bt = g_bt[img];
    const int lane = threadIdx.x & 31;
    const int gw = (blockIdx.x * blockDim.x + threadIdx.x) >> 5;
    const int nw = (gridDim.x * blockDim.x) >> 5;

    for (int p = gw; p < NP; p += nw) {
        float logs = g_logs[img * NP + p];
        if (binf(-logs) < bt) continue;   // row max score = -logs
        float m = g_m[img * NP + p];
        const float* row = logits + ((size_t)img * NP + p) * NC;
#pragma unroll
        for (int k = 0; k < 3; k++) {
            int cc = lane + 32 * k;
            if (cc >= 1 && cc < NC) {
                float sc = (row[cc] - m) - logs;
                if (binf(sc) >= bt) {
                    int pos = atomicAdd(&g_cnt[img], 1);
                    if (pos < CAP) {
                        unsigned int flat = (unsigned int)(p * CM1 + (cc - 1));
                        g_cand[img * CAP + pos] =
                            ((unsigned long long)okey(sc) << 32) | (unsigned int)(~flat);
                    }
                }
            }
        }
    }
}

// ---------------- K4: per-image sort + decode + NMS + output ----------------
struct SmemFinal {
    unsigned long long cand[CAP];
    float bx[NCAND][4];
    float obx[NCAND][4];
    float sc[NCAND];
    int   lb[NCAND];
    float area[NCAND];
    int   keep[NCAND];
    int   kidx[NOUT];
    float red[512];
};

__global__ void k_final(const float* __restrict__ bbox,
                        const float* __restrict__ priors,
                        float* __restrict__ out) {
    extern __shared__ char smraw[];
    SmemFinal& S = *reinterpret_cast<SmemFinal*>(smraw);
    const int img = blockIdx.x;
    const int tid = threadIdx.x;
    const int nthr = blockDim.x;

    int n = g_cnt[img];
    if (n > CAP) n = CAP;
    for (int i = tid; i < n; i += nthr) S.cand[i] = g_cand[img * CAP + i];
    int M = 512;
    while (M < n) M <<= 1;
    for (int i = tid; i < M; i += nthr)
        if (i >= n) S.cand[i] = 0ull;
    __syncthreads();

    // bitonic sort descending on packed (key, ~idx)
    for (int k = 2; k <= M; k <<= 1) {
        for (int j = k >> 1; j > 0; j >>= 1) {
            for (int i = tid; i < M; i += nthr) {
                int ixj = i ^ j;
                if (ixj > i) {
                    unsigned long long a = S.cand[i], b = S.cand[ixj];
                    bool sw = ((i & k) == 0) ? (a < b) : (a > b);
                    if (sw) { S.cand[i] = b; S.cand[ixj] = a; }
                }
            }
            __syncthreads();
        }
    }

    // top-400: unpack, decode boxes
    for (int r = tid; r < NCAND; r += nthr) {
        unsigned long long v = S.cand[r];
        unsigned int key = (unsigned int)(v >> 32);
        unsigned int fb = (key & 0x80000000u) ? (key ^ 0x80000000u) : ~key;
        float score = __uint_as_float(fb);
        int flat = (int)(~(unsigned int)(v & 0xffffffffu));
        int p = flat / CM1;
        int lbl = flat - p * CM1 + 1;
        const float* loc = bbox + ((size_t)img * NP + p) * 4;
        float px = priors[p * 4 + 0], py = priors[p * 4 + 1];
        float pw = priors[p * 4 + 2], ph = priors[p * 4 + 3];
        float cx = loc[0] * 0.1f * pw + px;
        float cy = loc[1] * 0.1f * ph + py;
        float w = expf(loc[2] * 0.2f) * pw;
        float h = expf(loc[3] * 0.2f) * ph;
        S.bx[r][0] = (cx - w * 0.5f) * 512.0f;
        S.bx[r][1] = (cy - h * 0.5f) * 512.0f;
        S.bx[r][2] = (cx + w * 0.5f) * 512.0f;
        S.bx[r][3] = (cy + h * 0.5f) * 512.0f;
        S.sc[r] = score;
        S.lb[r] = lbl;
        S.keep[r] = 1;
    }
    __syncthreads();

    // max over all coords
    float mx = -INFINITY;
    for (int i = tid; i < NCAND * 4; i += nthr) mx = fmaxf(mx, ((float*)S.bx)[i]);
    S.red[tid] = mx;
    __syncthreads();
    for (int o = nthr >> 1; o; o >>= 1) {
        if (tid < o) S.red[tid] = fmaxf(S.red[tid], S.red[tid + o]);
        __syncthreads();
    }
    float maxc = S.red[0];

    // class-offset boxes + areas (on offset boxes, matching reference rounding)
    for (int r = tid; r < NCAND; r += nthr) {
        float off = (float)S.lb[r] * (maxc + 1.0f);
        float x1 = S.bx[r][0] + off, y1 = S.bx[r][1] + off;
        float x2 = S.bx[r][2] + off, y2 = S.bx[r][3] + off;
        S.obx[r][0] = x1; S.obx[r][1] = y1; S.obx[r][2] = x2; S.obx[r][3] = y2;
        S.area[r] = (x2 - x1) * (y2 - y1);
    }
    __syncthreads();

    // greedy NMS
    for (int i = 0; i < NCAND; i++) {
        if (S.keep[i]) {
            int j = tid;
            if (j < NCAND && j > i) {
                float lt0 = fmaxf(S.obx[i][0], S.obx[j][0]);
                float lt1 = fmaxf(S.obx[i][1], S.obx[j][1]);
                float rb0 = fminf(S.obx[i][2], S.obx[j][2]);
                float rb1 = fminf(S.obx[i][3], S.obx[j][3]);
                float w = fmaxf(rb0 - lt0, 0.0f);
                float h = fmaxf(rb1 - lt1, 0.0f);
                float inter = w * h;
                float uni = S.area[i] + S.area[j] - inter;
                float iou = inter / fmaxf(uni, 1e-12f);
                if (iou > 0.45f) S.keep[j] = 0;
            }
        }
        __syncthreads();
    }

    // first 100 kept (score order), then first non-kept as padding
    if (tid == 0) {
        int c = 0;
        for (int i = 0; i < NCAND && c < NOUT; i++) if (S.keep[i]) S.kidx[c++] = i;
        for (int i = 0; i < NCAND && c < NOUT; i++) if (!S.keep[i]) S.kidx[c++] = i;
    }
    __syncthreads();

    // outputs: boxes [16,100,4] | labels(float) [16,100] | scores [16,100]
    for (int r = tid; r < NOUT; r += nthr) {
        int i = S.kidx[r];
        float* ob = out + ((size_t)img * NOUT + r) * 4;
        ob[0] = S.bx[i][0]; ob[1] = S.bx[i][1]; ob[2] = S.bx[i][2]; ob[3] = S.bx[i][3];
        out[NB * NOUT * 4 + img * NOUT + r] = (float)S.lb[i];
        out[NB * NOUT * 5 + img * NOUT + r] = S.keep[i] ? S.sc[i] : -INFINITY;
    }
}

// ---------------- launch ----------------
extern "C" void kernel_launch(void* const* d_in, const int* in_sizes, int n_in,
                              void* d_out, int out_size) {
    const float* logits = (const float*)d_in[0];
    const float* bbox   = (const float*)d_in[1];
    const float* priors = (const float*)d_in[2];
    float* out = (float*)d_out;

    int zt = NB * NBINS;
    k_zero<<<(zt + 255) / 256, 256>>>();
    k_lse_hist<<<dim3(256, NB), 256>>>(logits);
    k_thresh<<<NB, 32>>>();
    k_compact<<<dim3(64, NB), 256>>>(logits);
    cudaFuncSetAttribute(k_final, cudaFuncAttributeMaxDynamicSharedMemorySize,
                         (int)sizeof(SmemFinal));
    k_final<<<NB, 512, sizeof(SmemFinal)>>>(bbox, priors, out);
}

// round 2
// speedup vs baseline: 2.0118x; 2.0118x over previous
#include <cuda_runtime.h>
#include <math.h>

#define NB    16
#define NP    32768
#define NC    81
#define CM1   80
#define NBINS 2048
#define CAP   8192
#define NCAND 400
#define NOUT  100

// ---------------- scratch (static device globals; no allocation) ----------------
__device__ float              g_m[NB * NP];
__device__ float              g_logs[NB * NP];
__device__ float              g_rowsc[NB * NP];
__device__ unsigned int       g_hist[NB * NBINS];
__device__ int                g_bt[NB];
__device__ int                g_cnt[NB];
__device__ unsigned long long g_cand[NB * CAP];

__device__ __forceinline__ int binf(float s) {
    int b = (int)floorf((s + 30.0f) * (NBINS / 40.0f));
    b = b < 0 ? 0 : b;
    b = b > (NBINS - 1) ? (NBINS - 1) : b;
    return b;
}

__device__ __forceinline__ unsigned int okey(float s) {
    unsigned int u = __float_as_uint(s);
    return (u & 0x80000000u) ? ~u : (u | 0x80000000u);
}

// ---------------- K0: zero hist + counters ----------------
__global__ void k_zero() {
    int i = blockIdx.x * blockDim.x + threadIdx.x;
    if (i < NB * NBINS) g_hist[i] = 0u;
    if (i < NB) g_cnt[i] = 0;
}

// ---------------- K1: fused logsumexp + PER-ROW fg-max histogram ----------------
// warp per row of 81 logits; lane loads c, c+32, c+64; ONE atomic per row.
__global__ void k_lse_hist(const float* __restrict__ logits) {
    const int img = blockIdx.y;
    const int lane = threadIdx.x & 31;
    const int gw = (blockIdx.x * blockDim.x + threadIdx.x) >> 5;
    const int nw = (gridDim.x * blockDim.x) >> 5;

    for (int p = gw; p < NP; p += nw) {
        const float* row = logits + ((size_t)img * NP + p) * NC;
        float a = row[lane];
        float b = row[lane + 32];
        float c = (lane < 17) ? row[lane + 64] : -INFINITY;
        float fa = (lane == 0) ? -INFINITY : a;     // exclude background for fg-max
        float m = fmaxf(fmaxf(a, b), c);
        float fg = fmaxf(fmaxf(fa, b), c);
#pragma unroll
        for (int o = 16; o; o >>= 1) {
            m = fmaxf(m, __shfl_xor_sync(0xffffffffu, m, o));
            fg = fmaxf(fg, __shfl_xor_sync(0xffffffffu, fg, o));
        }
        float s = expf(a - m) + expf(b - m);
        if (lane < 17) s += expf(c - m);
#pragma unroll
        for (int o = 16; o; o >>= 1) s += __shfl_xor_sync(0xffffffffu, s, o);
        if (lane == 0) {
            float logs = logf(s);
            float rs = (fg - m) - logs;             // row's best foreground score
            int idx = img * NP + p;
            g_m[idx] = m;
            g_logs[idx] = logs;
            g_rowsc[idx] = rs;
            atomicAdd(&g_hist[img * NBINS + binf(rs)], 1u);
        }
    }
}

// ---------------- K2: parallel threshold find (cum from top >= 400) ----------------
__global__ void k_thresh() {
    __shared__ unsigned int part[256];
    const int img = blockIdx.x;
    const int t = threadIdx.x;
    const int hi = NBINS - 1 - 8 * t;   // chunk t covers bins hi .. hi-7 (descending)
    unsigned int v[8];
    unsigned int s = 0;
#pragma unroll
    for (int k = 0; k < 8; k++) { v[k] = g_hist[img * NBINS + hi - k]; s += v[k]; }
    part[t] = s;
    __syncthreads();
    // inclusive prefix over t (Hillis-Steele)
    for (int o = 1; o < 256; o <<= 1) {
        unsigned int y = (t >= o) ? part[t - o] : 0u;
        __syncthreads();
        part[t] += y;
        __syncthreads();
    }
    unsigned int incl = part[t];
    unsigned int excl = incl - s;
    if (excl < NCAND && incl >= NCAND) {
        unsigned int cum = excl;
#pragma unroll
        for (int k = 0; k < 8; k++) {
            cum += v[k];
            if (cum >= NCAND) { g_bt[img] = hi - k; break; }
        }
    }
    if (t == 255 && incl < NCAND) g_bt[img] = 0;   // fallback (never expected)
}

// ---------------- K3: compact candidates from qualifying rows ----------------
__global__ void k_compact(const float* __restrict__ logits) {
    const int img = blockIdx.y;
    const int bt = g_bt[img];
    const int lane = threadIdx.x & 31;
    const int tid = blockIdx.x * blockDim.x + threadIdx.x;
    const int stride = gridDim.x * blockDim.x;

    for (int p0 = tid; p0 < NP; p0 += stride) {
        float rs = g_rowsc[img * NP + p0];
        bool flag = (binf(rs) >= bt);
        unsigned int mask = __ballot_sync(0xffffffffu, flag);
        while (mask) {
            int src = __ffs(mask) - 1;
            mask &= mask - 1;
            int pp = __shfl_sync(0xffffffffu, p0, src);
            float m = g_m[img * NP + pp];
            float logs = g_logs[img * NP + pp];
            const float* row = logits + ((size_t)img * NP + pp) * NC;
#pragma unroll
            for (int k = 0; k < 3; k++) {
                int cc = lane + 32 * k;
                if (cc >= 1 && cc < NC) {
                    float sc = (row[cc] - m) - logs;
                    if (binf(sc) >= bt) {
                        int pos = atomicAdd(&g_cnt[img], 1);
                        if (pos < CAP) {
                            unsigned int flat = (unsigned int)(pp * CM1 + (cc - 1));
                            g_cand[img * CAP + pos] =
                                ((unsigned long long)okey(sc) << 32) | (unsigned int)(~flat);
                        }
                    }
                }
            }
        }
    }
}

// ---------------- K4: per-image sort + decode + bitmask NMS + output ----------------
struct SmemFinal {
    unsigned long long cand[CAP];
    float bx[NCAND][4];
    float obx[NCAND][4];
    float sc[NCAND];
    int   lb[NCAND];
    float area[NCAND];
    unsigned int adj[NCAND][16];   // suppression bitmatrix (j > i bits)
    unsigned int keepw[16];
    int   keep[NCAND];
    int   kidx[NOUT];
    float red[512];
};

__global__ void k_final(const float* __restrict__ bbox,
                        const float* __restrict__ priors,
                        float* __restrict__ out) {
    extern __shared__ char smraw[];
    SmemFinal& S = *reinterpret_cast<SmemFinal*>(smraw);
    const int img = blockIdx.x;
    const int tid = threadIdx.x;
    const int nthr = blockDim.x;

    int n = g_cnt[img];
    if (n > CAP) n = CAP;
    for (int i = tid; i < n; i += nthr) S.cand[i] = g_cand[img * CAP + i];
    int M = 512;
    while (M < n) M <<= 1;
    for (int i = tid; i < M; i += nthr)
        if (i >= n) S.cand[i] = 0ull;
    __syncthreads();

    // bitonic sort descending on packed (key, ~idx)
    for (int k = 2; k <= M; k <<= 1) {
        for (int j = k >> 1; j > 0; j >>= 1) {
            for (int i = tid; i < M; i += nthr) {
                int ixj = i ^ j;
                if (ixj > i) {
                    unsigned long long a = S.cand[i], b = S.cand[ixj];
                    bool sw = ((i & k) == 0) ? (a < b) : (a > b);
                    if (sw) { S.cand[i] = b; S.cand[ixj] = a; }
                }
            }
            __syncthreads();
        }
    }

    // top-400: unpack, decode boxes
    for (int r = tid; r < NCAND; r += nthr) {
        unsigned long long v = S.cand[r];
        unsigned int key = (unsigned int)(v >> 32);
        unsigned int fb = (key & 0x80000000u) ? (key ^ 0x80000000u) : ~key;
        float score = __uint_as_float(fb);
        int flat = (int)(~(unsigned int)(v & 0xffffffffu));
        int p = flat / CM1;
        int lbl = flat - p * CM1 + 1;
        const float* loc = bbox + ((size_t)img * NP + p) * 4;
        float px = priors[p * 4 + 0], py = priors[p * 4 + 1];
        float pw = priors[p * 4 + 2], ph = priors[p * 4 + 3];
        float cx = loc[0] * 0.1f * pw + px;
        float cy = loc[1] * 0.1f * ph + py;
        float w = expf(loc[2] * 0.2f) * pw;
        float h = expf(loc[3] * 0.2f) * ph;
        S.bx[r][0] = (cx - w * 0.5f) * 512.0f;
        S.bx[r][1] = (cy - h * 0.5f) * 512.0f;
        S.bx[r][2] = (cx + w * 0.5f) * 512.0f;
        S.bx[r][3] = (cy + h * 0.5f) * 512.0f;
        S.sc[r] = score;
        S.lb[r] = lbl;
    }
    // zero adjacency
    for (int i = tid; i < NCAND * 16; i += nthr) ((unsigned int*)S.adj)[i] = 0u;
    __syncthreads();

    // max over all coords
    float mx = -INFINITY;
    for (int i = tid; i < NCAND * 4; i += nthr) mx = fmaxf(mx, ((float*)S.bx)[i]);
    S.red[tid] = mx;
    __syncthreads();
    for (int o = nthr >> 1; o; o >>= 1) {
        if (tid < o) S.red[tid] = fmaxf(S.red[tid], S.red[tid + o]);
        __syncthreads();
    }
    float maxc = S.red[0];

    // class-offset boxes + areas (on offset boxes, matching reference rounding)
    for (int r = tid; r < NCAND; r += nthr) {
        float off = (float)S.lb[r] * (maxc + 1.0f);
        float x1 = S.bx[r][0] + off, y1 = S.bx[r][1] + off;
        float x2 = S.bx[r][2] + off, y2 = S.bx[r][3] + off;
        S.obx[r][0] = x1; S.obx[r][1] = y1; S.obx[r][2] = x2; S.obx[r][3] = y2;
        S.area[r] = (x2 - x1) * (y2 - y1);
    }
    __syncthreads();

    // build suppression bitmatrix: adj[i] bit j set iff j > i and IoU > 0.45
    for (int idx = tid; idx < NCAND * NCAND; idx += nthr) {
        int i = idx / NCAND, j = idx % NCAND;
        if (j > i) {
            float lt0 = fmaxf(S.obx[i][0], S.obx[j][0]);
            float lt1 = fmaxf(S.obx[i][1], S.obx[j][1]);
            float rb0 = fminf(S.obx[i][2], S.obx[j][2]);
            float rb1 = fminf(S.obx[i][3], S.obx[j][3]);
            float w = fmaxf(rb0 - lt0, 0.0f);
            float h = fmaxf(rb1 - lt1, 0.0f);
            float inter = w * h;
            float uni = S.area[i] + S.area[j] - inter;
            float iou = inter / fmaxf(uni, 1e-12f);
            if (iou > 0.45f) atomicOr(&S.adj[i][j >> 5], 1u << (j & 31));
        }
    }
    __syncthreads();

    // greedy NMS on warp 0: 13 keep-words held in lanes 0..12
    if (tid < 32) {
        unsigned int kw;
        if (tid < 12) kw = 0xffffffffu;
        else if (tid == 12) kw = 0x0000ffffu;   // bits 384..399 valid
        else kw = 0u;
        for (int i = 0; i < NCAND; i++) {
            unsigned int w = __shfl_sync(0xffffffffu, kw, i >> 5);
            if ((w >> (i & 31)) & 1u) {
                if (tid < 13) kw &= ~S.adj[i][tid];
            }
        }
        if (tid < 13) S.keepw[tid] = kw;
    }
    __syncthreads();
    for (int i = tid; i < NCAND; i += nthr)
        S.keep[i] = (S.keepw[i >> 5] >> (i & 31)) & 1u;
    __syncthreads();

    // first 100 kept (score order), then first non-kept as padding
    if (tid == 0) {
        int c = 0;
        for (int i = 0; i < NCAND && c < NOUT; i++) if (S.keep[i]) S.kidx[c++] = i;
        for (int i = 0; i < NCAND && c < NOUT; i++) if (!S.keep[i]) S.kidx[c++] = i;
    }
    __syncthreads();

    // outputs: boxes [16,100,4] | labels(float) [16,100] | scores [16,100]
    for (int r = tid; r < NOUT; r += nthr) {
        int i = S.kidx[r];
        float* ob = out + ((size_t)img * NOUT + r) * 4;
        ob[0] = S.bx[i][0]; ob[1] = S.bx[i][1]; ob[2] = S.bx[i][2]; ob[3] = S.bx[i][3];
        out[NB * NOUT * 4 + img * NOUT + r] = (float)S.lb[i];
        out[NB * NOUT * 5 + img * NOUT + r] = S.keep[i] ? S.sc[i] : -INFINITY;
    }
}

// ---------------- launch ----------------
extern "C" void kernel_launch(void* const* d_in, const int* in_sizes, int n_in,
                              void* d_out, int out_size) {
    const float* logits = (const float*)d_in[0];
    const float* bbox   = (const float*)d_in[1];
    const float* priors = (const float*)d_in[2];
    float* out = (float*)d_out;

    int zt = NB * NBINS + NB;
    k_zero<<<(zt + 255) / 256, 256>>>();
    k_lse_hist<<<dim3(64, NB), 256>>>(logits);
    k_thresh<<<NB, 256>>>();
    k_compact<<<dim3(32, NB), 256>>>(logits);
    cudaFuncSetAttribute(k_final, cudaFuncAttributeMaxDynamicSharedMemorySize,
                         (int)sizeof(SmemFinal));
    k_final<<<NB, 512, sizeof(SmemFinal)>>>(bbox, priors, out);
}

// round 3
// speedup vs baseline: 2.5322x; 1.2587x over previous
#include <cuda_runtime.h>
#include <math.h>

#define NB    16
#define NP    32768
#define NC    81
#define CM1   80
#define NBINS 2048
#define CAP   8192
#define NCAND 400
#define NOUT  100
#define NTHR  1024

// ---------------- scratch (static device globals; no allocation) ----------------
__device__ float              g_m[NB * NP];
__device__ float              g_logs[NB * NP];
__device__ float              g_rowsc[NB * NP];
__device__ unsigned int       g_hist[NB * NBINS];
__device__ int                g_bt[NB];
__device__ int                g_cnt[NB];
__device__ unsigned long long g_cand[NB * CAP];

__device__ __forceinline__ int binf(float s) {
    int b = (int)floorf((s + 30.0f) * (NBINS / 40.0f));
    b = b < 0 ? 0 : b;
    b = b > (NBINS - 1) ? (NBINS - 1) : b;
    return b;
}

__device__ __forceinline__ unsigned int okey(float s) {
    unsigned int u = __float_as_uint(s);
    return (u & 0x80000000u) ? ~u : (u | 0x80000000u);
}

// ---------------- K0: zero hist + counters ----------------
__global__ void k_zero() {
    int i = blockIdx.x * blockDim.x + threadIdx.x;
    if (i < NB * NBINS) g_hist[i] = 0u;
    if (i < NB) g_cnt[i] = 0;
}

// ---------------- K1: fused logsumexp + PER-ROW fg-max histogram ----------------
__global__ void k_lse_hist(const float* __restrict__ logits) {
    const int img = blockIdx.y;
    const int lane = threadIdx.x & 31;
    const int gw = (blockIdx.x * blockDim.x + threadIdx.x) >> 5;
    const int nw = (gridDim.x * blockDim.x) >> 5;

    for (int p = gw; p < NP; p += nw) {
        const float* row = logits + ((size_t)img * NP + p) * NC;
        float a = row[lane];
        float b = row[lane + 32];
        float c = (lane < 17) ? row[lane + 64] : -INFINITY;
        float fa = (lane == 0) ? -INFINITY : a;     // exclude background for fg-max
        float m = fmaxf(fmaxf(a, b), c);
        float fg = fmaxf(fmaxf(fa, b), c);
#pragma unroll
        for (int o = 16; o; o >>= 1) {
            m = fmaxf(m, __shfl_xor_sync(0xffffffffu, m, o));
            fg = fmaxf(fg, __shfl_xor_sync(0xffffffffu, fg, o));
        }
        float s = expf(a - m) + expf(b - m);
        if (lane < 17) s += expf(c - m);
#pragma unroll
        for (int o = 16; o; o >>= 1) s += __shfl_xor_sync(0xffffffffu, s, o);
        if (lane == 0) {
            float logs = logf(s);
            float rs = (fg - m) - logs;             // row's best foreground score
            int idx = img * NP + p;
            g_m[idx] = m;
            g_logs[idx] = logs;
            g_rowsc[idx] = rs;
            atomicAdd(&g_hist[img * NBINS + binf(rs)], 1u);
        }
    }
}

// ---------------- K2: parallel threshold find (cum from top >= 400) ----------------
__global__ void k_thresh() {
    __shared__ unsigned int part[256];
    const int img = blockIdx.x;
    const int t = threadIdx.x;
    const int hi = NBINS - 1 - 8 * t;   // chunk t covers bins hi .. hi-7 (descending)
    unsigned int v[8];
    unsigned int s = 0;
#pragma unroll
    for (int k = 0; k < 8; k++) { v[k] = g_hist[img * NBINS + hi - k]; s += v[k]; }
    part[t] = s;
    __syncthreads();
    for (int o = 1; o < 256; o <<= 1) {
        unsigned int y = (t >= o) ? part[t - o] : 0u;
        __syncthreads();
        part[t] += y;
        __syncthreads();
    }
    unsigned int incl = part[t];
    unsigned int excl = incl - s;
    if (excl < NCAND && incl >= NCAND) {
        unsigned int cum = excl;
#pragma unroll
        for (int k = 0; k < 8; k++) {
            cum += v[k];
            if (cum >= NCAND) { g_bt[img] = hi - k; break; }
        }
    }
    if (t == 255 && incl < NCAND) g_bt[img] = 0;   // fallback (never expected)
}

// ---------------- K3: compact candidates (1 row per thread, warp-cooperative emit) ----
__global__ void k_compact(const float* __restrict__ logits) {
    const int img = blockIdx.y;
    const int bt = g_bt[img];
    const int lane = threadIdx.x & 31;
    const int p0 = blockIdx.x * blockDim.x + threadIdx.x;   // exactly covers NP

    float rs = g_rowsc[img * NP + p0];
    bool flag = (binf(rs) >= bt);
    unsigned int mask = __ballot_sync(0xffffffffu, flag);
    while (mask) {
        int src = __ffs(mask) - 1;
        mask &= mask - 1;
        int pp = __shfl_sync(0xffffffffu, p0, src);
        float m = g_m[img * NP + pp];
        float logs = g_logs[img * NP + pp];
        const float* row = logits + ((size_t)img * NP + pp) * NC;
#pragma unroll
        for (int k = 0; k < 3; k++) {
            int cc = lane + 32 * k;
            if (cc >= 1 && cc < NC) {
                float sc = (row[cc] - m) - logs;
                if (binf(sc) >= bt) {
                    int pos = atomicAdd(&g_cnt[img], 1);
                    if (pos < CAP) {
                        unsigned int flat = (unsigned int)(pp * CM1 + (cc - 1));
                        g_cand[img * CAP + pos] =
                            ((unsigned long long)okey(sc) << 32) | (unsigned int)(~flat);
                    }
                }
            }
        }
    }
}

// ---------------- K4: per-image sort + decode + bitmask NMS + output ----------------
struct SmemFinal {
    unsigned long long cand[CAP];      // 64 KB
    float4 obx4[NCAND];                // offset boxes, SoA float4 (conflict-free LDS.128)
    float bx[NCAND][4];
    float sc[NCAND];
    int   lb[NCAND];
    float area[NCAND];
    unsigned int adj[NCAND][13];       // suppression bitmatrix (j > i bits)
    unsigned int keepw[13];
    int   wpre[14];
    int   kidx[NOUT];
    float red[NTHR];
};

__global__ void __launch_bounds__(NTHR, 1)
k_final(const float* __restrict__ bbox,
        const float* __restrict__ priors,
        float* __restrict__ out) {
    extern __shared__ char smraw[];
    SmemFinal& S = *reinterpret_cast<SmemFinal*>(smraw);
    const int img = blockIdx.x;
    const int tid = threadIdx.x;
    const int lane = tid & 31;
    const int warp = tid >> 5;

    int n = g_cnt[img];
    if (n > CAP) n = CAP;
    for (int i = tid; i < n; i += NTHR) S.cand[i] = g_cand[img * CAP + i];
    int M = 1024;
    while (M < n) M <<= 1;
    for (int i = tid; i < M; i += NTHR)
        if (i >= n) S.cand[i] = 0ull;
    __syncthreads();

    // bitonic sort descending on packed (key, ~idx)
    for (int k = 2; k <= M; k <<= 1) {
        for (int j = k >> 1; j > 0; j >>= 1) {
            for (int i = tid; i < M; i += NTHR) {
                int ixj = i ^ j;
                if (ixj > i) {
                    unsigned long long a = S.cand[i], b = S.cand[ixj];
                    bool sw = ((i & k) == 0) ? (a < b) : (a > b);
                    if (sw) { S.cand[i] = b; S.cand[ixj] = a; }
                }
            }
            __syncthreads();
        }
    }

    // top-400: unpack, decode boxes
    if (tid < NCAND) {
        int r = tid;
        unsigned long long v = S.cand[r];
        unsigned int key = (unsigned int)(v >> 32);
        unsigned int fb = (key & 0x80000000u) ? (key ^ 0x80000000u) : ~key;
        float score = __uint_as_float(fb);
        int flat = (int)(~(unsigned int)(v & 0xffffffffu));
        int p = flat / CM1;
        int lbl = flat - p * CM1 + 1;
        const float* loc = bbox + ((size_t)img * NP + p) * 4;
        float px = priors[p * 4 + 0], py = priors[p * 4 + 1];
        float pw = priors[p * 4 + 2], ph = priors[p * 4 + 3];
        float cx = loc[0] * 0.1f * pw + px;
        float cy = loc[1] * 0.1f * ph + py;
        float w = expf(loc[2] * 0.2f) * pw;
        float h = expf(loc[3] * 0.2f) * ph;
        S.bx[r][0] = (cx - w * 0.5f) * 512.0f;
        S.bx[r][1] = (cy - h * 0.5f) * 512.0f;
        S.bx[r][2] = (cx + w * 0.5f) * 512.0f;
        S.bx[r][3] = (cy + h * 0.5f) * 512.0f;
        S.sc[r] = score;
        S.lb[r] = lbl;
    }
    __syncthreads();

    // max over all coords
    float mx = -INFINITY;
    for (int i = tid; i < NCAND * 4; i += NTHR) mx = fmaxf(mx, ((float*)S.bx)[i]);
    S.red[tid] = mx;
    __syncthreads();
    for (int o = NTHR >> 1; o; o >>= 1) {
        if (tid < o) S.red[tid] = fmaxf(S.red[tid], S.red[tid + o]);
        __syncthreads();
    }
    float maxc = S.red[0];

    // class-offset boxes (SoA float4) + areas on offset boxes (matches reference rounding)
    if (tid < NCAND) {
        int r = tid;
        float off = (float)S.lb[r] * (maxc + 1.0f);
        float x1 = S.bx[r][0] + off, y1 = S.bx[r][1] + off;
        float x2 = S.bx[r][2] + off, y2 = S.bx[r][3] + off;
        S.obx4[r] = make_float4(x1, y1, x2, y2);
        S.area[r] = (x2 - x1) * (y2 - y1);
    }
    __syncthreads();

    // adjacency: warp per i; lanes sweep j in 13 chunks of 32; ballot -> one STS, no atomics
    for (int i = warp; i < NCAND; i += NTHR / 32) {
        float4 bi = S.obx4[i];          // broadcast
        float ai = S.area[i];
#pragma unroll
        for (int w = 0; w < 13; w++) {
            int j = w * 32 + lane;
            bool pred = false;
            if (j < NCAND && j > i) {
                float4 bj = S.obx4[j];  // conflict-free LDS.128
                float lt0 = fmaxf(bi.x, bj.x);
                float lt1 = fmaxf(bi.y, bj.y);
                float rb0 = fminf(bi.z, bj.z);
                float rb1 = fminf(bi.w, bj.w);
                float ww = fmaxf(rb0 - lt0, 0.0f);
                float hh = fmaxf(rb1 - lt1, 0.0f);
                float inter = ww * hh;
                float uni = ai + S.area[j] - inter;
                pred = (inter / fmaxf(uni, 1e-12f)) > 0.45f;
            }
            unsigned int bits = __ballot_sync(0xffffffffu, pred);
            if (lane == 0) S.adj[i][w] = bits;
        }
    }
    __syncthreads();

    // greedy NMS on warp 0: 13 keep-words in lanes 0..12, prefetched adj rows
    if (tid < 32) {
        unsigned int kw;
        if (lane < 12) kw = 0xffffffffu;
        else if (lane == 12) kw = 0x0000ffffu;   // bits 384..399 valid
        else kw = 0u;
        unsigned int nextrow = (lane < 13) ? S.adj[0][lane] : 0u;
        for (int i = 0; i < NCAND; i++) {
            unsigned int row = nextrow;
            nextrow = (lane < 13 && i + 1 < NCAND) ? S.adj[i + 1][lane] : 0u;
            unsigned int w = __shfl_sync(0xffffffffu, kw, i >> 5);
            if ((w >> (i & 31)) & 1u) kw &= ~row;
        }
        if (lane < 13) S.keepw[lane] = kw;
    }
    __syncthreads();

    // parallel rank selection: first 100 kept (score order), pad with first non-kept
    if (tid == 0) {
        int s = 0;
#pragma unroll
        for (int w = 0; w < 13; w++) { S.wpre[w] = s; s += __popc(S.keepw[w]); }
        S.wpre[13] = s;
    }
    __syncthreads();
    int K = S.wpre[13];
    if (tid < NCAND) {
        int i = tid;
        unsigned int word = S.keepw[i >> 5];
        unsigned int below = word & ((1u << (i & 31)) - 1u);
        int kb = S.wpre[i >> 5] + __popc(below);
        if ((word >> (i & 31)) & 1u) {
            if (kb < NOUT) S.kidx[kb] = i;
        } else {
            int nr = i - kb;                 // rank among non-kept
            if (K + nr < NOUT) S.kidx[K + nr] = i;
        }
    }
    __syncthreads();

    // outputs: boxes [16,100,4] | labels(float) [16,100] | scores [16,100]
    if (tid < NOUT) {
        int r = tid;
        int i = S.kidx[r];
        bool kept = (S.keepw[i >> 5] >> (i & 31)) & 1u;
        float* ob = out + ((size_t)img * NOUT + r) * 4;
        ob[0] = S.bx[i][0]; ob[1] = S.bx[i][1]; ob[2] = S.bx[i][2]; ob[3] = S.bx[i][3];
        out[NB * NOUT * 4 + img * NOUT + r] = (float)S.lb[i];
        out[NB * NOUT * 5 + img * NOUT + r] = kept ? S.sc[i] : -INFINITY;
    }
}

// ---------------- launch ----------------
extern "C" void kernel_launch(void* const* d_in, const int* in_sizes, int n_in,
                              void* d_out, int out_size) {
    const float* logits = (const float*)d_in[0];
    const float* bbox   = (const float*)d_in[1];
    const float* priors = (const float*)d_in[2];
    float* out = (float*)d_out;

    int zt = NB * NBINS + NB;
    k_zero<<<(zt + 255) / 256, 256>>>();
    k_lse_hist<<<dim3(128, NB), 256>>>(logits);
    k_thresh<<<NB, 256>>>();
    k_compact<<<dim3(128, NB), 256>>>(logits);
    cudaFuncSetAttribute(k_final, cudaFuncAttributeMaxDynamicSharedMemorySize,
                         (int)sizeof(SmemFinal));
    k_final<<<NB, NTHR, sizeof(SmemFinal)>>>(bbox, priors, out);
}

// round 4
// speedup vs baseline: 2.5862x; 1.0213x over previous
#include <cuda_runtime.h>
#include <math.h>

#define NB    16
#define NP    32768
#define NC    81
#define CM1   80
#define NBINS 2048
#define SCAP  4096
#define RCAP  2048
#define NCAND 400
#define NOUT  100
#define NTHR  1024

// ---------------- scratch (static device globals; zero-initialized at load) --------
__device__ float        g_rowsc[NB * NP];
__device__ unsigned int g_hist[NB * NBINS];   // k_final re-zeroes after use

__device__ __forceinline__ int binf(float s) {
    int b = (int)floorf((s + 30.0f) * (NBINS / 40.0f));
    b = b < 0 ? 0 : b;
    b = b > (NBINS - 1) ? (NBINS - 1) : b;
    return b;
}

__device__ __forceinline__ unsigned int okey(float s) {
    unsigned int u = __float_as_uint(s);
    return (u & 0x80000000u) ? ~u : (u | 0x80000000u);
}

// ---------------- K1: approx row-score + histogram (2 rows/warp ILP) ----------------
__global__ void k_lse_hist(const float* __restrict__ logits) {
    const int img = blockIdx.y;
    const int lane = threadIdx.x & 31;
    const int gw = (blockIdx.x * blockDim.x + threadIdx.x) >> 5;
    const int nw = (gridDim.x * blockDim.x) >> 5;   // 4096 warps/image
    const float* base = logits + (size_t)img * NP * NC;

    for (int p0 = gw; p0 < NP; p0 += 2 * nw) {
        int p1 = p0 + nw;   // NP == 8*nw, always in range
        const float* r0 = base + (size_t)p0 * NC;
        const float* r1 = base + (size_t)p1 * NC;
        float a0 = r0[lane], b0 = r0[lane + 32];
        float a1 = r1[lane], b1 = r1[lane + 32];
        float c0 = (lane < 17) ? r0[lane + 64] : -INFINITY;
        float c1 = (lane < 17) ? r1[lane + 64] : -INFINITY;
        float fa0 = (lane == 0) ? -INFINITY : a0;
        float fa1 = (lane == 0) ? -INFINITY : a1;
        float m0 = fmaxf(fmaxf(a0, b0), c0), fg0 = fmaxf(fmaxf(fa0, b0), c0);
        float m1 = fmaxf(fmaxf(a1, b1), c1), fg1 = fmaxf(fmaxf(fa1, b1), c1);
#pragma unroll
        for (int o = 16; o; o >>= 1) {
            m0 = fmaxf(m0, __shfl_xor_sync(0xffffffffu, m0, o));
            m1 = fmaxf(m1, __shfl_xor_sync(0xffffffffu, m1, o));
            fg0 = fmaxf(fg0, __shfl_xor_sync(0xffffffffu, fg0, o));
            fg1 = fmaxf(fg1, __shfl_xor_sync(0xffffffffu, fg1, o));
        }
        float s0 = __expf(a0 - m0) + __expf(b0 - m0);
        float s1 = __expf(a1 - m1) + __expf(b1 - m1);
        if (lane < 17) { s0 += __expf(c0 - m0); s1 += __expf(c1 - m1); }
#pragma unroll
        for (int o = 16; o; o >>= 1) {
            s0 += __shfl_xor_sync(0xffffffffu, s0, o);
            s1 += __shfl_xor_sync(0xffffffffu, s1, o);
        }
        if (lane == 0) {
            float rs0 = (fg0 - m0) - __logf(s0);
            float rs1 = (fg1 - m1) - __logf(s1);
            g_rowsc[img * NP + p0] = rs0;
            g_rowsc[img * NP + p1] = rs1;
            atomicAdd(&g_hist[img * NBINS + binf(rs0)], 1u);
            atomicAdd(&g_hist[img * NBINS + binf(rs1)], 1u);
        }
    }
}

// ---------------- K4: threshold + compact + exact rescore + sort + NMS + output ----
struct SmemFinal {
    unsigned long long cand[SCAP];     // 32 KB
    int   rows[RCAP];                  // 8 KB
    float4 obx4[NCAND];
    float bx[NCAND][4];
    float sc[NCAND];
    int   lb[NCAND];
    float area[NCAND];
    unsigned int adj[NCAND][13];
    unsigned int keepw[13];
    int   wpre[14];
    int   kidx[NOUT];
    float red[NTHR];
    unsigned int scan[NTHR];
    int   nrows, ncand, btm;
};

__global__ void __launch_bounds__(NTHR, 1)
k_final(const float* __restrict__ logits,
        const float* __restrict__ bbox,
        const float* __restrict__ priors,
        float* __restrict__ out) {
    extern __shared__ char smraw[];
    SmemFinal& S = *reinterpret_cast<SmemFinal*>(smraw);
    const int img = blockIdx.x;
    const int tid = threadIdx.x;
    const int lane = tid & 31;
    const int warp = tid >> 5;

    if (tid == 0) { S.nrows = 0; S.ncand = 0; }

    // ---- phase 0: threshold from histogram (2 descending bins per thread) ----
    const int hi = NBINS - 1 - 2 * tid;
    unsigned int v0 = g_hist[img * NBINS + hi];
    unsigned int v1 = g_hist[img * NBINS + hi - 1];
    S.scan[tid] = v0 + v1;
    __syncthreads();
    for (int o = 1; o < NTHR; o <<= 1) {
        unsigned int y = (tid >= o) ? S.scan[tid - o] : 0u;
        __syncthreads();
        S.scan[tid] += y;
        __syncthreads();
    }
    {
        unsigned int incl = S.scan[tid], excl = incl - (v0 + v1);
        if (excl < NCAND && incl >= NCAND) {
            int bt = (excl + v0 >= NCAND) ? hi : hi - 1;
            S.btm = (bt > 0) ? bt - 1 : 0;     // one-bin safety margin
        }
        if (tid == NTHR - 1 && incl < NCAND) S.btm = 0;   // never expected
    }
    // re-zero histogram for the next graph replay
    g_hist[img * NBINS + hi] = 0u;
    g_hist[img * NBINS + hi - 1] = 0u;
    __syncthreads();
    const int btm = S.btm;

    // ---- phase 1: gather qualifying rows (float4 scan of approx row scores) ----
    const float4* rsc4 = (const float4*)(g_rowsc + (size_t)img * NP);
    for (int q = tid; q < NP / 4; q += NTHR) {
        float4 v = rsc4[q];
        int br = q * 4;
        if (binf(v.x) >= btm) { int pos = atomicAdd(&S.nrows, 1); if (pos < RCAP) S.rows[pos] = br; }
        if (binf(v.y) >= btm) { int pos = atomicAdd(&S.nrows, 1); if (pos < RCAP) S.rows[pos] = br + 1; }
        if (binf(v.z) >= btm) { int pos = atomicAdd(&S.nrows, 1); if (pos < RCAP) S.rows[pos] = br + 2; }
        if (binf(v.w) >= btm) { int pos = atomicAdd(&S.nrows, 1); if (pos < RCAP) S.rows[pos] = br + 3; }
    }
    __syncthreads();

    // ---- phase 2: exact rescoring of qualifying rows (warp per row) ----
    int nrows = S.nrows < RCAP ? S.nrows : RCAP;
    for (int ri = warp; ri < nrows; ri += NTHR / 32) {
        int p = S.rows[ri];
        const float* row = logits + ((size_t)img * NP + p) * NC;
        float a = row[lane];
        float b = row[lane + 32];
        float c = (lane < 17) ? row[lane + 64] : -INFINITY;
        float m = fmaxf(fmaxf(a, b), c);
#pragma unroll
        for (int o = 16; o; o >>= 1) m = fmaxf(m, __shfl_xor_sync(0xffffffffu, m, o));
        float s = expf(a - m) + expf(b - m);
        if (lane < 17) s += expf(c - m);
#pragma unroll
        for (int o = 16; o; o >>= 1) s += __shfl_xor_sync(0xffffffffu, s, o);
        float logs = logf(s);
#pragma unroll
        for (int k = 0; k < 3; k++) {
            int cc = lane + 32 * k;
            float x = (k == 0) ? a : (k == 1) ? b : c;
            if (cc >= 1 && cc < NC) {
                float scv = (x - m) - logs;
                if (binf(scv) >= btm) {
                    int pos = atomicAdd(&S.ncand, 1);
                    if (pos < SCAP) {
                        unsigned int flat = (unsigned int)(p * CM1 + (cc - 1));
                        S.cand[pos] =
                            ((unsigned long long)okey(scv) << 32) | (unsigned int)(~flat);
                    }
                }
            }
        }
    }
    __syncthreads();

    // ---- phase 3: bitonic sort descending on packed (key, ~idx) ----
    int n = S.ncand < SCAP ? S.ncand : SCAP;
    int M = 1024;
    while (M < n) M <<= 1;
    for (int i = tid; i < M; i += NTHR)
        if (i >= n) S.cand[i] = 0ull;
    __syncthreads();
    for (int k = 2; k <= M; k <<= 1) {
        for (int j = k >> 1; j > 0; j >>= 1) {
            for (int i = tid; i < M; i += NTHR) {
                int ixj = i ^ j;
                if (ixj > i) {
                    unsigned long long a = S.cand[i], b = S.cand[ixj];
                    bool sw = ((i & k) == 0) ? (a < b) : (a > b);
                    if (sw) { S.cand[i] = b; S.cand[ixj] = a; }
                }
            }
            __syncthreads();
        }
    }

    // ---- phase 4: top-400 unpack + box decode ----
    if (tid < NCAND) {
        int r = tid;
        unsigned long long v = S.cand[r];
        unsigned int key = (unsigned int)(v >> 32);
        unsigned int fb = (key & 0x80000000u) ? (key ^ 0x80000000u) : ~key;
        float score = __uint_as_float(fb);
        int flat = (int)(~(unsigned int)(v & 0xffffffffu));
        int p = flat / CM1;
        int lbl = flat - p * CM1 + 1;
        const float* loc = bbox + ((size_t)img * NP + p) * 4;
        float px = priors[p * 4 + 0], py = priors[p * 4 + 1];
        float pw = priors[p * 4 + 2], ph = priors[p * 4 + 3];
        float cx = loc[0] * 0.1f * pw + px;
        float cy = loc[1] * 0.1f * ph + py;
        float w = expf(loc[2] * 0.2f) * pw;
        float h = expf(loc[3] * 0.2f) * ph;
        S.bx[r][0] = (cx - w * 0.5f) * 512.0f;
        S.bx[r][1] = (cy - h * 0.5f) * 512.0f;
        S.bx[r][2] = (cx + w * 0.5f) * 512.0f;
        S.bx[r][3] = (cy + h * 0.5f) * 512.0f;
        S.sc[r] = score;
        S.lb[r] = lbl;
    }
    __syncthreads();

    // max over all coords
    float mx = -INFINITY;
    for (int i = tid; i < NCAND * 4; i += NTHR) mx = fmaxf(mx, ((float*)S.bx)[i]);
    S.red[tid] = mx;
    __syncthreads();
    for (int o = NTHR >> 1; o; o >>= 1) {
        if (tid < o) S.red[tid] = fmaxf(S.red[tid], S.red[tid + o]);
        __syncthreads();
    }
    float maxc = S.red[0];

    // class-offset boxes (SoA float4) + areas on offset boxes
    if (tid < NCAND) {
        int r = tid;
        float off = (float)S.lb[r] * (maxc + 1.0f);
        float x1 = S.bx[r][0] + off, y1 = S.bx[r][1] + off;
        float x2 = S.bx[r][2] + off, y2 = S.bx[r][3] + off;
        S.obx4[r] = make_float4(x1, y1, x2, y2);
        S.area[r] = (x2 - x1) * (y2 - y1);
    }
    __syncthreads();

    // ---- phase 5: adjacency bitmatrix (warp per i, ballot, no atomics) ----
    for (int i = warp; i < NCAND; i += NTHR / 32) {
        float4 bi = S.obx4[i];
        float ai = S.area[i];
#pragma unroll
        for (int w = 0; w < 13; w++) {
            int j = w * 32 + lane;
            bool pred = false;
            if (j < NCAND && j > i) {
                float4 bj = S.obx4[j];
                float lt0 = fmaxf(bi.x, bj.x);
                float lt1 = fmaxf(bi.y, bj.y);
                float rb0 = fminf(bi.z, bj.z);
                float rb1 = fminf(bi.w, bj.w);
                float ww = fmaxf(rb0 - lt0, 0.0f);
                float hh = fmaxf(rb1 - lt1, 0.0f);
                float inter = ww * hh;
                float uni = ai + S.area[j] - inter;
                pred = (inter / fmaxf(uni, 1e-12f)) > 0.45f;
            }
            unsigned int bits = __ballot_sync(0xffffffffu, pred);
            if (lane == 0) S.adj[i][w] = bits;
        }
    }
    __syncthreads();

    // ---- phase 6: greedy NMS on warp 0 (13 keep-words, prefetched rows) ----
    if (tid < 32) {
        unsigned int kw;
        if (lane < 12) kw = 0xffffffffu;
        else if (lane == 12) kw = 0x0000ffffu;
        else kw = 0u;
        unsigned int nextrow = (lane < 13) ? S.adj[0][lane] : 0u;
        for (int i = 0; i < NCAND; i++) {
            unsigned int row = nextrow;
            nextrow = (lane < 13 && i + 1 < NCAND) ? S.adj[i + 1][lane] : 0u;
            unsigned int w = __shfl_sync(0xffffffffu, kw, i >> 5);
            if ((w >> (i & 31)) & 1u) kw &= ~row;
        }
        if (lane < 13) S.keepw[lane] = kw;
    }
    __syncthreads();

    // ---- phase 7: parallel rank select + output ----
    if (tid == 0) {
        int s = 0;
#pragma unroll
        for (int w = 0; w < 13; w++) { S.wpre[w] = s; s += __popc(S.keepw[w]); }
        S.wpre[13] = s;
    }
    __syncthreads();
    int K = S.wpre[13];
    if (tid < NCAND) {
        int i = tid;
        unsigned int word = S.keepw[i >> 5];
        unsigned int below = word & ((1u << (i & 31)) - 1u);
        int kb = S.wpre[i >> 5] + __popc(below);
        if ((word >> (i & 31)) & 1u) {
            if (kb < NOUT) S.kidx[kb] = i;
        } else {
            int nr = i - kb;
            if (K + nr < NOUT) S.kidx[K + nr] = i;
        }
    }
    __syncthreads();

    if (tid < NOUT) {
        int r = tid;
        int i = S.kidx[r];
        bool kept = (S.keepw[i >> 5] >> (i & 31)) & 1u;
        float* ob = out + ((size_t)img * NOUT + r) * 4;
        ob[0] = S.bx[i][0]; ob[1] = S.bx[i][1]; ob[2] = S.bx[i][2]; ob[3] = S.bx[i][3];
        out[NB * NOUT * 4 + img * NOUT + r] = (float)S.lb[i];
        out[NB * NOUT * 5 + img * NOUT + r] = kept ? S.sc[i] : -INFINITY;
    }
}

// ---------------- launch ----------------
extern "C" void kernel_launch(void* const* d_in, const int* in_sizes, int n_in,
                              void* d_out, int out_size) {
    const float* logits = (const float*)d_in[0];
    const float* bbox   = (const float*)d_in[1];
    const float* priors = (const float*)d_in[2];
    float* out = (float*)d_out;

    k_lse_hist<<<dim3(512, NB), 256>>>(logits);
    cudaFuncSetAttribute(k_final, cudaFuncAttributeMaxDynamicSharedMemorySize,
                         (int)sizeof(SmemFinal));
    k_final<<<NB, NTHR, sizeof(SmemFinal)>>>(logits, bbox, priors, out);
}

// round 5
// speedup vs baseline: 2.7054x; 1.0461x over previous
#include <cuda_runtime.h>
#include <math.h>

#define NB    16
#define NP    32768
#define NC    81
#define CM1   80
#define NBINS 2048
#define SCAP  4096
#define RCAP  2048
#define NCAND 400
#define NOUT  100
#define NTHR  1024

// ---------------- scratch (static device globals; zero-initialized at load) --------
__device__ float        g_rowsc[NB * NP];
__device__ unsigned int g_hist[NB * NBINS];   // k_final re-zeroes after use

__device__ __forceinline__ int binf(float s) {
    int b = (int)floorf((s + 30.0f) * (NBINS / 40.0f));
    b = b < 0 ? 0 : b;
    b = b > (NBINS - 1) ? (NBINS - 1) : b;
    return b;
}

__device__ __forceinline__ unsigned int okey(float s) {
    unsigned int u = __float_as_uint(s);
    return (u & 0x80000000u) ? ~u : (u | 0x80000000u);
}

// ---------------- K1: approx row-score + histogram (no max-subtraction) ----------------
// rs = max_fg(x) - log(sum exp(x)); logits are O(1) so exp() cannot overflow in fp32.
__global__ void k_lse_hist(const float* __restrict__ logits) {
    const int img = blockIdx.y;
    const int lane = threadIdx.x & 31;
    const int gw = (blockIdx.x * blockDim.x + threadIdx.x) >> 5;
    const int nw = (gridDim.x * blockDim.x) >> 5;   // 4096 warps/image
    const float* base = logits + (size_t)img * NP * NC;

    for (int p0 = gw; p0 < NP; p0 += 2 * nw) {
        int p1 = p0 + nw;   // NP == 8*nw, always in range
        const float* r0 = base + (size_t)p0 * NC;
        const float* r1 = base + (size_t)p1 * NC;
        float a0 = r0[lane], b0 = r0[lane + 32];
        float a1 = r1[lane], b1 = r1[lane + 32];
        bool t3 = (lane < 17);
        float c0 = t3 ? r0[lane + 64] : -INFINITY;
        float c1 = t3 ? r1[lane + 64] : -INFINITY;
        float fa0 = (lane == 0) ? -INFINITY : a0;   // exclude background from fg-max
        float fa1 = (lane == 0) ? -INFINITY : a1;
        float fg0 = fmaxf(fmaxf(fa0, b0), c0);
        float fg1 = fmaxf(fmaxf(fa1, b1), c1);
        float s0 = __expf(a0) + __expf(b0) + (t3 ? __expf(c0) : 0.0f);
        float s1 = __expf(a1) + __expf(b1) + (t3 ? __expf(c1) : 0.0f);
#pragma unroll
        for (int o = 16; o; o >>= 1) {
            fg0 = fmaxf(fg0, __shfl_xor_sync(0xffffffffu, fg0, o));
            fg1 = fmaxf(fg1, __shfl_xor_sync(0xffffffffu, fg1, o));
            s0 += __shfl_xor_sync(0xffffffffu, s0, o);
            s1 += __shfl_xor_sync(0xffffffffu, s1, o);
        }
        if (lane == 0) {
            float rs0 = fg0 - __logf(s0);
            float rs1 = fg1 - __logf(s1);
            g_rowsc[img * NP + p0] = rs0;
            g_rowsc[img * NP + p1] = rs1;
            atomicAdd(&g_hist[img * NBINS + binf(rs0)], 1u);
            atomicAdd(&g_hist[img * NBINS + binf(rs1)], 1u);
        }
    }
}

// ---------------- K4: threshold + compact + exact rescore + sort + NMS + output ----
struct SmemFinal {
    unsigned long long cand[SCAP];     // 32 KB
    int   rows[RCAP];                  // 8 KB
    float4 obx4[NCAND];
    float bx[NCAND][4];
    float sc[NCAND];
    int   lb[NCAND];
    float area[NCAND];
    unsigned int adj[NCAND][13];
    unsigned int keepw[13];
    int   wpre[14];
    int   kidx[NOUT];
    float red[NTHR];
    unsigned int scan[32];
    int   nrows, ncand, btm;
};

__global__ void __launch_bounds__(NTHR, 1)
k_final(const float* __restrict__ logits,
        const float* __restrict__ bbox,
        const float* __restrict__ priors,
        float* __restrict__ out) {
    extern __shared__ char smraw[];
    SmemFinal& S = *reinterpret_cast<SmemFinal*>(smraw);
    const int img = blockIdx.x;
    const int tid = threadIdx.x;
    const int lane = tid & 31;
    const int warp = tid >> 5;

    if (tid == 0) { S.nrows = 0; S.ncand = 0; }

    // ---- phase 0: threshold from histogram; two-level warp scan (2 barriers) ----
    const int hi = NBINS - 1 - 2 * tid;
    unsigned int v0 = g_hist[img * NBINS + hi];
    unsigned int v1 = g_hist[img * NBINS + hi - 1];
    unsigned int s = v0 + v1;
    unsigned int x = s;
#pragma unroll
    for (int o = 1; o < 32; o <<= 1) {
        unsigned int y = __shfl_up_sync(0xffffffffu, x, o);
        if (lane >= o) x += y;
    }
    if (lane == 31) S.scan[warp] = x;
    __syncthreads();
    if (warp == 0) {
        unsigned int t = S.scan[lane];
        unsigned int tx = t;
#pragma unroll
        for (int o = 1; o < 32; o <<= 1) {
            unsigned int y = __shfl_up_sync(0xffffffffu, tx, o);
            if (lane >= o) tx += y;
        }
        S.scan[lane] = tx - t;   // exclusive warp offsets
    }
    __syncthreads();
    {
        unsigned int incl = x + S.scan[warp];
        unsigned int excl = incl - s;
        if (excl < NCAND && incl >= NCAND) {
            int bt = (excl + v0 >= NCAND) ? hi : hi - 1;
            S.btm = (bt > 0) ? bt - 1 : 0;     // one-bin safety margin
        }
        if (tid == NTHR - 1 && incl < NCAND) S.btm = 0;   // never expected
    }
    // re-zero histogram for the next graph replay
    g_hist[img * NBINS + hi] = 0u;
    g_hist[img * NBINS + hi - 1] = 0u;
    __syncthreads();
    const int btm = S.btm;

    // ---- phase 1: gather qualifying rows (float4 scan of approx row scores) ----
    const float4* rsc4 = (const float4*)(g_rowsc + (size_t)img * NP);
    for (int q = tid; q < NP / 4; q += NTHR) {
        float4 v = rsc4[q];
        int br = q * 4;
        if (binf(v.x) >= btm) { int pos = atomicAdd(&S.nrows, 1); if (pos < RCAP) S.rows[pos] = br; }
        if (binf(v.y) >= btm) { int pos = atomicAdd(&S.nrows, 1); if (pos < RCAP) S.rows[pos] = br + 1; }
        if (binf(v.z) >= btm) { int pos = atomicAdd(&S.nrows, 1); if (pos < RCAP) S.rows[pos] = br + 2; }
        if (binf(v.w) >= btm) { int pos = atomicAdd(&S.nrows, 1); if (pos < RCAP) S.rows[pos] = br + 3; }
    }
    __syncthreads();

    // ---- phase 2: exact rescoring of qualifying rows (warp per row) ----
    int nrows = S.nrows < RCAP ? S.nrows : RCAP;
    for (int ri = warp; ri < nrows; ri += NTHR / 32) {
        int p = S.rows[ri];
        const float* row = logits + ((size_t)img * NP + p) * NC;
        float a = row[lane];
        float b = row[lane + 32];
        float c = (lane < 17) ? row[lane + 64] : -INFINITY;
        float m = fmaxf(fmaxf(a, b), c);
#pragma unroll
        for (int o = 16; o; o >>= 1) m = fmaxf(m, __shfl_xor_sync(0xffffffffu, m, o));
        float sv = expf(a - m) + expf(b - m);
        if (lane < 17) sv += expf(c - m);
#pragma unroll
        for (int o = 16; o; o >>= 1) sv += __shfl_xor_sync(0xffffffffu, sv, o);
        float logs = logf(sv);
#pragma unroll
        for (int k = 0; k < 3; k++) {
            int cc = lane + 32 * k;
            float xv = (k == 0) ? a : (k == 1) ? b : c;
            if (cc >= 1 && cc < NC) {
                float scv = (xv - m) - logs;
                if (binf(scv) >= btm) {
                    int pos = atomicAdd(&S.ncand, 1);
                    if (pos < SCAP) {
                        unsigned int flat = (unsigned int)(p * CM1 + (cc - 1));
                        S.cand[pos] =
                            ((unsigned long long)okey(scv) << 32) | (unsigned int)(~flat);
                    }
                }
            }
        }
    }
    __syncthreads();

    // ---- phase 3: bitonic sort descending on packed (key, ~idx) ----
    int n = S.ncand < SCAP ? S.ncand : SCAP;
    int M = 512;
    while (M < n) M <<= 1;
    for (int i = tid; i < M; i += NTHR)
        if (i >= n) S.cand[i] = 0ull;
    __syncthreads();
    for (int k = 2; k <= M; k <<= 1) {
        for (int j = k >> 1; j > 0; j >>= 1) {
            for (int i = tid; i < M; i += NTHR) {
                int ixj = i ^ j;
                if (ixj > i) {
                    unsigned long long a = S.cand[i], b = S.cand[ixj];
                    bool sw = ((i & k) == 0) ? (a < b) : (a > b);
                    if (sw) { S.cand[i] = b; S.cand[ixj] = a; }
                }
            }
            __syncthreads();
        }
    }

    // ---- phase 4: top-400 unpack + box decode ----
    if (tid < NCAND) {
        int r = tid;
        unsigned long long v = S.cand[r];
        unsigned int key = (unsigned int)(v >> 32);
        unsigned int fb = (key & 0x80000000u) ? (key ^ 0x80000000u) : ~key;
        float score = __uint_as_float(fb);
        int flat = (int)(~(unsigned int)(v & 0xffffffffu));
        int p = flat / CM1;
        int lbl = flat - p * CM1 + 1;
        const float* loc = bbox + ((size_t)img * NP + p) * 4;
        float px = priors[p * 4 + 0], py = priors[p * 4 + 1];
        float pw = priors[p * 4 + 2], ph = priors[p * 4 + 3];
        float cx = loc[0] * 0.1f * pw + px;
        float cy = loc[1] * 0.1f * ph + py;
        float w = expf(loc[2] * 0.2f) * pw;
        float h = expf(loc[3] * 0.2f) * ph;
        S.bx[r][0] = (cx - w * 0.5f) * 512.0f;
        S.bx[r][1] = (cy - h * 0.5f) * 512.0f;
        S.bx[r][2] = (cx + w * 0.5f) * 512.0f;
        S.bx[r][3] = (cy + h * 0.5f) * 512.0f;
        S.sc[r] = score;
        S.lb[r] = lbl;
    }
    __syncthreads();

    // max over all coords
    float mx = -INFINITY;
    for (int i = tid; i < NCAND * 4; i += NTHR) mx = fmaxf(mx, ((float*)S.bx)[i]);
    S.red[tid] = mx;
    __syncthreads();
    for (int o = NTHR >> 1; o; o >>= 1) {
        if (tid < o) S.red[tid] = fmaxf(S.red[tid], S.red[tid + o]);
        __syncthreads();
    }
    float maxc = S.red[0];

    // class-offset boxes (SoA float4) + areas on offset boxes
    if (tid < NCAND) {
        int r = tid;
        float off = (float)S.lb[r] * (maxc + 1.0f);
        float x1 = S.bx[r][0] + off, y1 = S.bx[r][1] + off;
        float x2 = S.bx[r][2] + off, y2 = S.bx[r][3] + off;
        S.obx4[r] = make_float4(x1, y1, x2, y2);
        S.area[r] = (x2 - x1) * (y2 - y1);
    }
    __syncthreads();

    // ---- phase 5: adjacency bitmatrix, only words w >= i>>5 (j < i impossible) ----
    for (int i = warp; i < NCAND; i += NTHR / 32) {
        float4 bi = S.obx4[i];
        float ai = S.area[i];
        for (int w = i >> 5; w < 13; w++) {
            int j = w * 32 + lane;
            bool pred = false;
            if (j < NCAND && j > i) {
                float4 bj = S.obx4[j];
                float lt0 = fmaxf(bi.x, bj.x);
                float lt1 = fmaxf(bi.y, bj.y);
                float rb0 = fminf(bi.z, bj.z);
                float rb1 = fminf(bi.w, bj.w);
                float ww = fmaxf(rb0 - lt0, 0.0f);
                float hh = fmaxf(rb1 - lt1, 0.0f);
                float inter = ww * hh;
                float uni = ai + S.area[j] - inter;
                pred = (inter / fmaxf(uni, 1e-12f)) > 0.45f;
            }
            unsigned int bits = __ballot_sync(0xffffffffu, pred);
            if (lane == 0) S.adj[i][w] = bits;
        }
    }
    __syncthreads();

    // ---- phase 6: greedy NMS on warp 0 (13 keep-words, prefetched rows) ----
    if (tid < 32) {
        unsigned int kw;
        if (lane < 12) kw = 0xffffffffu;
        else if (lane == 12) kw = 0x0000ffffu;
        else kw = 0u;
        unsigned int nextrow = (lane < 13) ? S.adj[0][lane] : 0u;   // (0>>5)==0
        for (int i = 0; i < NCAND; i++) {
            unsigned int row = nextrow;
            nextrow = (lane < 13 && lane >= ((i + 1) >> 5) && i + 1 < NCAND)
                          ? S.adj[i + 1][lane] : 0u;
            unsigned int w = __shfl_sync(0xffffffffu, kw, i >> 5);
            if ((w >> (i & 31)) & 1u) kw &= ~row;
        }
        if (lane < 13) S.keepw[lane] = kw;
    }
    __syncthreads();

    // ---- phase 7: parallel rank select + output ----
    if (tid == 0) {
        int sacc = 0;
#pragma unroll
        for (int w = 0; w < 13; w++) { S.wpre[w] = sacc; sacc += __popc(S.keepw[w]); }
        S.wpre[13] = sacc;
    }
    __syncthreads();
    int K = S.wpre[13];
    if (tid < NCAND) {
        int i = tid;
        unsigned int word = S.keepw[i >> 5];
        unsigned int below = word & ((1u << (i & 31)) - 1u);
        int kb = S.wpre[i >> 5] + __popc(below);
        if ((word >> (i & 31)) & 1u) {
            if (kb < NOUT) S.kidx[kb] = i;
        } else {
            int nr = i - kb;
            if (K + nr < NOUT) S.kidx[K + nr] = i;
        }
    }
    __syncthreads();

    if (tid < NOUT) {
        int r = tid;
        int i = S.kidx[r];
        bool kept = (S.keepw[i >> 5] >> (i & 31)) & 1u;
        float* ob = out + ((size_t)img * NOUT + r) * 4;
        ob[0] = S.bx[i][0]; ob[1] = S.bx[i][1]; ob[2] = S.bx[i][2]; ob[3] = S.bx[i][3];
        out[NB * NOUT * 4 + img * NOUT + r] = (float)S.lb[i];
        out[NB * NOUT * 5 + img * NOUT + r] = kept ? S.sc[i] : -INFINITY;
    }
}

// ---------------- launch ----------------
extern "C" void kernel_launch(void* const* d_in, const int* in_sizes, int n_in,
                              void* d_out, int out_size) {
    const float* logits = (const float*)d_in[0];
    const float* bbox   = (const float*)d_in[1];
    const float* priors = (const float*)d_in[2];
    float* out = (float*)d_out;

    k_lse_hist<<<dim3(512, NB), 256>>>(logits);
    cudaFuncSetAttribute(k_final, cudaFuncAttributeMaxDynamicSharedMemorySize,
                         (int)sizeof(SmemFinal));
    k_final<<<NB, NTHR, sizeof(SmemFinal)>>>(logits, bbox, priors, out);
}